// round 10
// baseline (speedup 1.0000x reference)
#include <cuda_runtime.h>

#define VOCAB 500
#define EMB   64
#define HID   64
#define BATCH 512
#define SEQ   512
#define ROWS_PER_CTA 4

// Precomputed input projection: E'[v][i] = b_ih0[i] + sum_j emb[v][j]*W_ih0[i][j]
__device__ float g_xproj[VOCAB * HID];

typedef unsigned long long u64;

__device__ __forceinline__ void fma2(u64 &d, u64 a, u64 b) {
    asm("fma.rn.f32x2 %0, %1, %2, %0;" : "+l"(d) : "l"(a), "l"(b));
}
__device__ __forceinline__ u64 add2(u64 a, u64 b) {
    u64 r; asm("add.rn.f32x2 %0, %1, %2;" : "=l"(r) : "l"(a), "l"(b)); return r;
}
__device__ __forceinline__ float hsum1(u64 a) {
    float lo, hi;
    asm("mov.b64 {%0,%1}, %2;" : "=f"(lo), "=f"(hi) : "l"(a));
    return lo + hi;
}
__device__ __forceinline__ float fast_tanh(float x) {
    float e = __expf(2.0f * x);
    return 1.0f - __fdividef(2.0f, e + 1.0f);
}
// Row barrier: syncs the 128 threads (4 warps) of one row.
__device__ __forceinline__ void bar_row(int row) {
    asm volatile("bar.sync %0, 128;" :: "r"(row + 1) : "memory");
}

// ---------------------------------------------------------------------------
// Kernel 1: fold embedding + layer-0 input projection into a 500x64 LUT.
// ---------------------------------------------------------------------------
__global__ void xproj_kernel(const float* __restrict__ emb,
                             const float* __restrict__ W_ih0,
                             const float* __restrict__ b_ih0) {
    __shared__ float se[EMB];
    const int v = blockIdx.x;
    const int i = threadIdx.x;
    se[i] = emb[v * EMB + i];
    __syncthreads();
    float acc = 0.0f;
    const float4* wr = (const float4*)(W_ih0 + i * EMB);
    #pragma unroll
    for (int q = 0; q < 16; q++) {
        float4 wv = __ldg(wr + q);
        acc += wv.x * se[4*q+0] + wv.y * se[4*q+1] + wv.z * se[4*q+2] + wv.w * se[4*q+3];
    }
    g_xproj[v * HID + i] = acc + b_ih0[i];
}

// ---------------------------------------------------------------------------
// Kernel 2: sequential scan. CTA = 512 threads = 4 rows x 128; grid = 128
// (1 CTA/SM; each SMSP carries 4 warps from 4 independently-synced rows).
// Thread = (row, i, jh). j-split is CHUNK-INTERLEAVED: lane jh owns float4
// chunks c = 2m + jh, so a lane pair's LDS.128 addresses are 16B apart ->
// same 128B line, one wavefront per warp-load (R9's padded halves cost 2).
// Weights: 3 x 32 floats = 96 regs. ONE named barrier per step (h1 and h2
// both double-buffered). Dual accumulators shorten each carried fma chain
// to 8 deep; s+r combine before the butterfly -> 2 shfls per step.
// Rows enter the loop STAGGERED (~row x 150 cyc dependent-FMA delay) so the
// 4 rows per SMSP pipeline their LDS/FMA/MUFU bursts instead of convoying.
// ---------------------------------------------------------------------------
__global__ void __launch_bounds__(512, 1)
scan_kernel(const int* __restrict__ xw,
            const float* __restrict__ W_hh0,
            const float* __restrict__ b_hh0,
            const float* __restrict__ W_ih1,
            const float* __restrict__ W_hh1,
            const float* __restrict__ b_ih1,
            const float* __restrict__ b_hh1,
            const float* __restrict__ fc_w,
            const float* __restrict__ fc_b,
            float* __restrict__ out) {
    __shared__ __align__(16) float sh1[2][ROWS_PER_CTA][HID];
    __shared__ __align__(16) float sh2[2][ROWS_PER_CTA][HID];
    __shared__ int   sidx[ROWS_PER_CTA * SEQ];
    __shared__ float swsum[ROWS_PER_CTA][4];
    __shared__ int   s_is64;

    const int tid  = threadIdx.x;
    const int row  = tid >> 7;            // 0..3
    const int gt   = tid & 127;
    const int i    = gt >> 1;             // owned output 0..63
    const int jh   = gt & 1;              // chunk-parity selector
    const int rbase = blockIdx.x * ROWS_PER_CTA;

    // --- weights: row i, interleaved chunks c = 2m+jh (3 x 16 u64) ---
    u64 w0[16], w1[16], w2[16];           // W_hh0, W_ih1, W_hh1
    {
        const u64* q0 = (const u64*)(W_hh0 + i * HID);
        const u64* q1 = (const u64*)(W_ih1 + i * HID);
        const u64* q2 = (const u64*)(W_hh1 + i * HID);
        #pragma unroll
        for (int m = 0; m < 8; m++) {
            const int c = 2 * m + jh;     // float4-chunk index, u64 pair {2c,2c+1}
            w0[2*m]   = __ldg(q0 + 2*c);  w0[2*m+1] = __ldg(q0 + 2*c + 1);
            w1[2*m]   = __ldg(q1 + 2*c);  w1[2*m+1] = __ldg(q1 + 2*c + 1);
            w2[2*m]   = __ldg(q2 + 2*c);  w2[2*m+1] = __ldg(q2 + 2*c + 1);
        }
    }
    const float bia1 = b_hh0[i];
    const float bia2 = b_ih1[i] + b_hh1[i];

    // --- dtype probe on GLOBAL first 128 words (valid for either layout) ---
    if (tid == 0) {
        int z = 0;
        #pragma unroll
        for (int k = 1; k < 128; k += 2) z |= xw[k];
        s_is64 = (z == 0);
    }
    // zero h buffers
    for (int k = tid; k < 2 * ROWS_PER_CTA * HID; k += 512) {
        (&sh1[0][0][0])[k] = 0.0f;
        (&sh2[0][0][0])[k] = 0.0f;
    }
    __syncthreads();
    {
        const int is64 = s_is64;
        const int base = rbase * SEQ;
        for (int k = tid; k < ROWS_PER_CTA * SEQ; k += 512) {
            int v = is64 ? xw[2 * (base + k)] : xw[base + k];
            sidx[k] = min(max(v, 0), VOCAB - 1);
        }
    }
    __syncthreads();

    const int* my_ix = sidx + row * SEQ;
    float cq  = 0.0f;                      // Whh0 . h1_prev (full sum)
    float xn  = __ldg(&g_xproj[my_ix[0] * HID + i]);
    float h2n = 0.0f;

    // --- phase stagger: desynchronize the 4 rows (convoy breaker) ---
    {
        float zz = 1.0f;
        #pragma unroll 1
        for (int k = 0; k < (row << 4); k++)
            asm volatile("fma.rn.f32 %0, %0, 0f3F800000, 0f00000000;" : "+f"(zz));
        xn = fmaf(zz, 0.0f, xn);           // consume zz (adds exact 0)
    }

    #pragma unroll 1
    for (int t = 0; t < SEQ; t++) {
        const int cur = t & 1;
        const float xc = xn;
        const int tn = (t + 1 < SEQ) ? (t + 1) : (SEQ - 1);
        xn = __ldg(&g_xproj[my_ix[tn] * HID + i]);   // prefetch next input

        // h1_t = tanh(Whh0.h1_{t-1} + x_t + b1)   (redundant across pair)
        const float h1n = fast_tanh(cq + xc + bia1);
        if (jh == 0) sh1[cur][row][i] = h1n;
        bar_row(row);   // the ONLY barrier in the step

        // merged region: s = Wih1.h1_t, q = Whh0.h1_t, r = Whh1.h2_{t-1}
        // dual accumulators -> 8-deep chains; 1-wavefront LDS per warp-load
        const ulonglong2* H1 = (const ulonglong2*)sh1[cur][row];
        const ulonglong2* H2 = (const ulonglong2*)sh2[cur ^ 1][row];
        u64 s0 = 0, s1 = 0, q0 = 0, q1 = 0, r0 = 0, r1 = 0;
        #pragma unroll
        for (int m = 0; m < 8; m++) {
            ulonglong2 ha = H1[2*m + jh];
            ulonglong2 ga = H2[2*m + jh];
            fma2(q0, w0[2*m],   ha.x);
            fma2(q1, w0[2*m+1], ha.y);
            fma2(s0, w1[2*m],   ha.x);
            fma2(s1, w1[2*m+1], ha.y);
            fma2(r0, w2[2*m],   ga.x);
            fma2(r1, w2[2*m+1], ga.y);
        }
        cq = hsum1(add2(q0, q1));
        cq += __shfl_xor_sync(0xffffffffu, cq, 1);
        float u = hsum1(add2(s0, s1)) + hsum1(add2(r0, r1));
        u += __shfl_xor_sync(0xffffffffu, u, 1);

        // h2_t = tanh(Wih1.h1_t + Whh1.h2_{t-1} + b2) -> buffer cur
        h2n = fast_tanh(u + bia2);
        if (jh == 0) sh2[cur][row][i] = h2n;
        // no second barrier: next step's bar_row orders this write before
        // its readers; H2 reads of buffer cur^1 precede its overwrite at t+2.
    }

    // --- final projection: out[b] = fc_w . h2 + fc_b ---
    const float fw = __ldg(&fc_w[i]);
    float val = (jh == 0) ? fw * h2n : 0.0f;
    #pragma unroll
    for (int off = 16; off; off >>= 1)
        val += __shfl_xor_sync(0xffffffffu, val, off);
    const int wing = (tid >> 5) & 3;
    if ((tid & 31) == 0) swsum[row][wing] = val;
    __syncthreads();
    if (tid < ROWS_PER_CTA)
        out[rbase + tid] = swsum[tid][0] + swsum[tid][1] +
                           swsum[tid][2] + swsum[tid][3] + fc_b[0];
}

// ---------------------------------------------------------------------------
extern "C" void kernel_launch(void* const* d_in, const int* in_sizes, int n_in,
                              void* d_out, int out_size) {
    const int*   x_raw = (const int*)d_in[0];
    const float* emb   = (const float*)d_in[1];
    const float* W_ih0 = (const float*)d_in[2];
    const float* W_hh0 = (const float*)d_in[3];
    const float* b_ih0 = (const float*)d_in[4];
    const float* b_hh0 = (const float*)d_in[5];
    const float* W_ih1 = (const float*)d_in[6];
    const float* W_hh1 = (const float*)d_in[7];
    const float* b_ih1 = (const float*)d_in[8];
    const float* b_hh1 = (const float*)d_in[9];
    const float* fc_w  = (const float*)d_in[10];
    const float* fc_b  = (const float*)d_in[11];
    float*       out   = (float*)d_out;

    xproj_kernel<<<VOCAB, HID>>>(emb, W_ih0, b_ih0);
    scan_kernel<<<BATCH / ROWS_PER_CTA, 512>>>(
        x_raw, W_hh0, b_hh0, W_ih1, W_hh1, b_ih1, b_hh1, fc_w, fc_b, out);
}

// round 11
// speedup vs baseline: 1.2688x; 1.2688x over previous
#include <cuda_runtime.h>

#define VOCAB 500
#define EMB   64
#define HID   64
#define BATCH 512
#define SEQ   512
#define ROWS_PER_CTA 2   // 2-row CTAs; 2 CTAs co-resident per SM

// Precomputed input projection: E'[v][i] = b_ih0[i] + sum_j emb[v][j]*W_ih0[i][j]
__device__ float g_xproj[VOCAB * HID];

typedef unsigned long long u64;

__device__ __forceinline__ void fma2(u64 &d, u64 a, u64 b) {
    asm("fma.rn.f32x2 %0, %1, %2, %0;" : "+l"(d) : "l"(a), "l"(b));
}
__device__ __forceinline__ u64 add2(u64 a, u64 b) {
    u64 r; asm("add.rn.f32x2 %0, %1, %2;" : "=l"(r) : "l"(a), "l"(b)); return r;
}
__device__ __forceinline__ float hsum2(u64 a, u64 b) {
    u64 s = add2(a, b);
    float lo, hi;
    asm("mov.b64 {%0,%1}, %2;" : "=f"(lo), "=f"(hi) : "l"(s));
    return lo + hi;
}
// HW tanh: MUFU.TANH, ~16 cyc, rel err ~2^-11 (vs ~45-cyc EX2+RCP chain)
__device__ __forceinline__ float fast_tanh(float x) {
    float r;
    asm("tanh.approx.f32 %0, %1;" : "=f"(r) : "f"(x));
    return r;
}

// ---------------------------------------------------------------------------
// Kernel 1: fold embedding + layer-0 input projection into a 500x64 LUT.
// ---------------------------------------------------------------------------
__global__ void xproj_kernel(const float* __restrict__ emb,
                             const float* __restrict__ W_ih0,
                             const float* __restrict__ b_ih0) {
    __shared__ float se[EMB];
    const int v = blockIdx.x;
    const int i = threadIdx.x;
    se[i] = emb[v * EMB + i];
    __syncthreads();
    float acc = 0.0f;
    const float4* wr = (const float4*)(W_ih0 + i * EMB);
    #pragma unroll
    for (int q = 0; q < 16; q++) {
        float4 wv = __ldg(wr + q);
        acc += wv.x * se[4*q+0] + wv.y * se[4*q+1] + wv.z * se[4*q+2] + wv.w * se[4*q+3];
    }
    g_xproj[v * HID + i] = acc + b_ih0[i];
}

// ---------------------------------------------------------------------------
// Kernel 2: sequential scan, R4 structure with 2-row CTAs.
// CTA = 128 threads = 2 rows x 64; grid = 256 -> 2 CTAs per SM (226 regs x
// 128 thr x 2 = 57.8K < 64K regfile). Each SMSP carries 2 warps from
// DIFFERENT CTAs (independent __syncthreads domains): while one CTA sits in
// barrier/tanh/LDS latency, the other's fma stream issues. __syncthreads
// (floor ~7 cyc) instead of named bars (~47 cyc) — the R7/R9/R10 named-bar
// experiments never beat R4's syncthreads. Thread owns output i with the
// FULL j range (no shfl); weights 3x64 floats = 192 regs; one pass over
// h1_new feeds both Wih1 (this step) and Whh0 (next step's recurrence).
// Both tanh's via MUFU.TANH. Index dtype (int64/int32) detected from the
// global first 128 words (in-bounds for both layouts).
// ---------------------------------------------------------------------------
__global__ void __launch_bounds__(64 * ROWS_PER_CTA, 2)
scan_kernel(const int* __restrict__ xw,
            const float* __restrict__ W_hh0,
            const float* __restrict__ b_hh0,
            const float* __restrict__ W_ih1,
            const float* __restrict__ W_hh1,
            const float* __restrict__ b_ih1,
            const float* __restrict__ b_hh1,
            const float* __restrict__ fc_w,
            const float* __restrict__ fc_b,
            float* __restrict__ out) {
    __shared__ __align__(16) float sh1[ROWS_PER_CTA][HID];
    __shared__ __align__(16) float sh2[ROWS_PER_CTA][HID];
    __shared__ int   sidx[ROWS_PER_CTA * SEQ];
    __shared__ float swsum[ROWS_PER_CTA][2];
    __shared__ int   s_is64;

    const int tid  = threadIdx.x;
    const int row  = tid >> 6;          // 0..1
    const int i    = tid & 63;          // owned output
    const int lane = tid & 31;
    const int half = (tid >> 5) & 1;    // warp within row
    const int rbase = blockIdx.x * ROWS_PER_CTA;

    // --- weights: full row i of each matrix, as f32x2 pairs (192 regs) ---
    u64 w0[32], w1[32], w2[32];         // W_hh0, W_ih1, W_hh1
    {
        const u64* q0 = (const u64*)(W_hh0 + i * HID);
        const u64* q1 = (const u64*)(W_ih1 + i * HID);
        const u64* q2 = (const u64*)(W_hh1 + i * HID);
        #pragma unroll
        for (int q = 0; q < 32; q++) {
            w0[q] = __ldg(q0 + q);
            w1[q] = __ldg(q1 + q);
            w2[q] = __ldg(q2 + q);
        }
    }
    const float b1 = b_hh0[i];
    const float b2 = b_ih1[i] + b_hh1[i];

    // --- dtype probe on GLOBAL first 128 words (valid for either layout) ---
    if (tid == 0) {
        int z = 0;
        #pragma unroll
        for (int k = 1; k < 128; k += 2) z |= xw[k];
        s_is64 = (z == 0);
    }
    __syncthreads();
    {
        const int is64 = s_is64;
        const int base = rbase * SEQ;
        for (int k = tid; k < ROWS_PER_CTA * SEQ; k += 64 * ROWS_PER_CTA) {
            int v = is64 ? xw[2 * (base + k)] : xw[base + k];
            sidx[k] = min(max(v, 0), VOCAB - 1);
        }
    }
    __syncthreads();

    float*      my_h1 = sh1[row];
    float*      my_h2 = sh2[row];
    const int*  my_ix = sidx + row * SEQ;
    const ulonglong2* H1 = (const ulonglong2*)my_h1;
    const ulonglong2* H2 = (const ulonglong2*)my_h2;

    // carried recurrent terms (h[-1] = 0)
    float c_q = 0.0f;                       // Whh0 . h1_prev
    float c_r = 0.0f;                       // Whh1 . h2_prev
    float xn  = __ldg(&g_xproj[my_ix[0] * HID + i]);
    float h2n = 0.0f;

    #pragma unroll 1
    for (int t = 0; t < SEQ; t++) {
        const float xc = xn;
        const int tn = (t + 1 < SEQ) ? (t + 1) : (SEQ - 1);
        xn = __ldg(&g_xproj[my_ix[tn] * HID + i]);   // prefetch next input

        // h1_new = tanh(Whh0.h1_prev + x_t + b1)
        const float h1n = fast_tanh(c_q + xc + b1);
        my_h1[i] = h1n;
        __syncthreads();   // B1: h1_new visible

        // one pass over h1_new feeds BOTH Wih1 (this step) and Whh0 (next)
        u64 s0 = 0, s1 = 0, q0 = 0, q1v = 0;
        #pragma unroll
        for (int m = 0; m < 16; m++) {
            ulonglong2 hv = H1[m];
            fma2(s0,  w1[2*m],   hv.x);
            fma2(s1,  w1[2*m+1], hv.y);
            fma2(q0,  w0[2*m],   hv.x);
            fma2(q1v, w0[2*m+1], hv.y);
        }
        const float s = hsum2(s0, s1);
        c_q = hsum2(q0, q1v);

        // h2_new = tanh(Wih1.h1_new + Whh1.h2_prev + b2)
        h2n = fast_tanh(s + c_r + b2);
        my_h2[i] = h2n;
        __syncthreads();   // B2: h2_new visible

        // recurrent term for next step: Whh1 . h2_new
        u64 r0 = 0, r1 = 0;
        #pragma unroll
        for (int m = 0; m < 16; m++) {
            ulonglong2 gv = H2[m];
            fma2(r0, w2[2*m],   gv.x);
            fma2(r1, w2[2*m+1], gv.y);
        }
        c_r = hsum2(r0, r1);
    }

    // --- final projection: out[b] = fc_w . h2 + fc_b ---
    float val = __ldg(&fc_w[i]) * h2n;
    #pragma unroll
    for (int off = 16; off; off >>= 1)
        val += __shfl_xor_sync(0xffffffffu, val, off);
    if (lane == 0) swsum[row][half] = val;
    __syncthreads();
    if (i == 0) out[rbase + row] = swsum[row][0] + swsum[row][1] + fc_b[0];
}

// ---------------------------------------------------------------------------
extern "C" void kernel_launch(void* const* d_in, const int* in_sizes, int n_in,
                              void* d_out, int out_size) {
    const int*   x_raw = (const int*)d_in[0];
    const float* emb   = (const float*)d_in[1];
    const float* W_ih0 = (const float*)d_in[2];
    const float* W_hh0 = (const float*)d_in[3];
    const float* b_ih0 = (const float*)d_in[4];
    const float* b_hh0 = (const float*)d_in[5];
    const float* W_ih1 = (const float*)d_in[6];
    const float* W_hh1 = (const float*)d_in[7];
    const float* b_ih1 = (const float*)d_in[8];
    const float* b_hh1 = (const float*)d_in[9];
    const float* fc_w  = (const float*)d_in[10];
    const float* fc_b  = (const float*)d_in[11];
    float*       out   = (float*)d_out;

    xproj_kernel<<<VOCAB, HID>>>(emb, W_ih0, b_ih0);
    scan_kernel<<<BATCH / ROWS_PER_CTA, 64 * ROWS_PER_CTA>>>(
        x_raw, W_hh0, b_hh0, W_ih1, W_hh1, b_ih1, b_hh1, fc_w, fc_b, out);
}

// round 12
// speedup vs baseline: 1.3818x; 1.0891x over previous
#include <cuda_runtime.h>

#define VOCAB 500
#define EMB   64
#define HID   64
#define BATCH 512
#define SEQ   512
#define ROWS_PER_CTA 2   // 2-row CTAs; 2 CTAs co-resident per SM

// Precomputed input projection: E'[v][i] = b_ih0[i] + sum_j emb[v][j]*W_ih0[i][j]
__device__ float g_xproj[VOCAB * HID];

typedef unsigned long long u64;

__device__ __forceinline__ void fma2(u64 &d, u64 a, u64 b) {
    asm("fma.rn.f32x2 %0, %1, %2, %0;" : "+l"(d) : "l"(a), "l"(b));
}
__device__ __forceinline__ u64 add2(u64 a, u64 b) {
    u64 r; asm("add.rn.f32x2 %0, %1, %2;" : "=l"(r) : "l"(a), "l"(b)); return r;
}
__device__ __forceinline__ float hsum2(u64 a, u64 b) {
    u64 s = add2(a, b);
    float lo, hi;
    asm("mov.b64 {%0,%1}, %2;" : "=f"(lo), "=f"(hi) : "l"(s));
    return lo + hi;
}
// HW tanh: MUFU.TANH, ~16 cyc, rel err ~2^-11 (vs ~45-cyc EX2+RCP chain)
__device__ __forceinline__ float fast_tanh(float x) {
    float r;
    asm("tanh.approx.f32 %0, %1;" : "=f"(r) : "f"(x));
    return r;
}

// ---------------------------------------------------------------------------
// Kernel 1: fold embedding + layer-0 input projection into a 500x64 LUT.
// ---------------------------------------------------------------------------
__global__ void xproj_kernel(const float* __restrict__ emb,
                             const float* __restrict__ W_ih0,
                             const float* __restrict__ b_ih0) {
    __shared__ float se[EMB];
    const int v = blockIdx.x;
    const int i = threadIdx.x;
    se[i] = emb[v * EMB + i];
    __syncthreads();
    float acc = 0.0f;
    const float4* wr = (const float4*)(W_ih0 + i * EMB);
    #pragma unroll
    for (int q = 0; q < 16; q++) {
        float4 wv = __ldg(wr + q);
        acc += wv.x * se[4*q+0] + wv.y * se[4*q+1] + wv.z * se[4*q+2] + wv.w * se[4*q+3];
    }
    g_xproj[v * HID + i] = acc + b_ih0[i];
}

// ---------------------------------------------------------------------------
// Kernel 2: sequential scan. CTA = 128 threads = 2 rows x 64; grid = 256 ->
// 2 CTAs per SM; each SMSP carries 2 warps from DIFFERENT __syncthreads
// domains, so one CTA's fma stream fills the other's barrier/LDS/MUFU
// latency. Thread owns output i with the FULL j range (no shfl); weights
// 3 x 64 floats = 192 regs.
// ONE barrier + ONE merged fma region per step: at iter t (cur = t&1) the
// thread stores h1_t AND h2_{t-1} into parity buffers [cur], syncs once,
// then computes s = Wih1.h1_t, q = Whh0.h1_t (next step's carry) and
// r = Whh1.h2_{t-1} in a single 96-fma2 region (6 round-robin accumulators).
// Race-free: reads of buffer [cur] at iter t finish before bar_{t+1}; the
// next write to that slot is at iter t+2, after bar_{t+1}. Iter 0 writes
// the zeros it reads (h_{-1} = 0), so no pre-zeroing is needed.
// Index dtype (int64/int32) detected from the global first 128 words.
// ---------------------------------------------------------------------------
__global__ void __launch_bounds__(64 * ROWS_PER_CTA, 2)
scan_kernel(const int* __restrict__ xw,
            const float* __restrict__ W_hh0,
            const float* __restrict__ b_hh0,
            const float* __restrict__ W_ih1,
            const float* __restrict__ W_hh1,
            const float* __restrict__ b_ih1,
            const float* __restrict__ b_hh1,
            const float* __restrict__ fc_w,
            const float* __restrict__ fc_b,
            float* __restrict__ out) {
    __shared__ __align__(16) float sh1[2][ROWS_PER_CTA][HID];
    __shared__ __align__(16) float sh2[2][ROWS_PER_CTA][HID];
    __shared__ int   sidx[ROWS_PER_CTA * SEQ];
    __shared__ float swsum[ROWS_PER_CTA][2];
    __shared__ int   s_is64;

    const int tid  = threadIdx.x;
    const int row  = tid >> 6;          // 0..1
    const int i    = tid & 63;          // owned output
    const int lane = tid & 31;
    const int half = (tid >> 5) & 1;    // warp within row
    const int rbase = blockIdx.x * ROWS_PER_CTA;

    // --- weights: full row i of each matrix, as f32x2 pairs (192 regs) ---
    u64 w0[32], w1[32], w2[32];         // W_hh0, W_ih1, W_hh1
    {
        const u64* q0 = (const u64*)(W_hh0 + i * HID);
        const u64* q1 = (const u64*)(W_ih1 + i * HID);
        const u64* q2 = (const u64*)(W_hh1 + i * HID);
        #pragma unroll
        for (int q = 0; q < 32; q++) {
            w0[q] = __ldg(q0 + q);
            w1[q] = __ldg(q1 + q);
            w2[q] = __ldg(q2 + q);
        }
    }
    const float b1 = b_hh0[i];
    const float b2 = b_ih1[i] + b_hh1[i];

    // --- dtype probe on GLOBAL first 128 words (valid for either layout) ---
    if (tid == 0) {
        int z = 0;
        #pragma unroll
        for (int k = 1; k < 128; k += 2) z |= xw[k];
        s_is64 = (z == 0);
    }
    __syncthreads();
    {
        const int is64 = s_is64;
        const int base = rbase * SEQ;
        for (int k = tid; k < ROWS_PER_CTA * SEQ; k += 64 * ROWS_PER_CTA) {
            int v = is64 ? xw[2 * (base + k)] : xw[base + k];
            sidx[k] = min(max(v, 0), VOCAB - 1);
        }
    }
    __syncthreads();

    const int* my_ix = sidx + row * SEQ;

    // carried state (h[-1] = 0): cq = Whh0.h1_prev, h2n = h2_prev
    float cq  = 0.0f;
    float h2n = 0.0f;
    float xn  = __ldg(&g_xproj[my_ix[0] * HID + i]);

    #pragma unroll 1
    for (int t = 0; t < SEQ; t++) {
        const int cur = t & 1;
        const float xc = xn;
        const int tn = (t + 1 < SEQ) ? (t + 1) : (SEQ - 1);
        xn = __ldg(&g_xproj[my_ix[tn] * HID + i]);   // prefetch next input

        // h1_t = tanh(Whh0.h1_{t-1} + x_t + b1); publish h1_t and h2_{t-1}
        const float h1n = fast_tanh(cq + xc + b1);
        sh1[cur][row][i] = h1n;
        sh2[cur][row][i] = h2n;
        __syncthreads();   // the ONLY barrier in the step

        // merged region: s = Wih1.h1_t, q = Whh0.h1_t (next step's carry),
        // r = Whh1.h2_{t-1} — 6 independent 16-deep fma2 chains
        const ulonglong2* H1 = (const ulonglong2*)sh1[cur][row];
        const ulonglong2* H2 = (const ulonglong2*)sh2[cur][row];
        u64 s0 = 0, s1 = 0, q0 = 0, q1v = 0, r0 = 0, r1 = 0;
        #pragma unroll
        for (int m = 0; m < 16; m++) {
            ulonglong2 ha = H1[m];
            fma2(s0,  w1[2*m],   ha.x);
            fma2(s1,  w1[2*m+1], ha.y);
            fma2(q0,  w0[2*m],   ha.x);
            fma2(q1v, w0[2*m+1], ha.y);
            ulonglong2 ga = H2[m];
            fma2(r0,  w2[2*m],   ga.x);
            fma2(r1,  w2[2*m+1], ga.y);
        }
        cq = hsum2(q0, q1v);
        // h2_t = tanh(Wih1.h1_t + Whh1.h2_{t-1} + b2) — published next iter
        h2n = fast_tanh(hsum2(s0, s1) + hsum2(r0, r1) + b2);
    }

    // --- final projection: out[b] = fc_w . h2 + fc_b ---
    float val = __ldg(&fc_w[i]) * h2n;
    #pragma unroll
    for (int off = 16; off; off >>= 1)
        val += __shfl_xor_sync(0xffffffffu, val, off);
    if (lane == 0) swsum[row][half] = val;
    __syncthreads();
    if (i == 0) out[rbase + row] = swsum[row][0] + swsum[row][1] + fc_b[0];
}

// ---------------------------------------------------------------------------
extern "C" void kernel_launch(void* const* d_in, const int* in_sizes, int n_in,
                              void* d_out, int out_size) {
    const int*   x_raw = (const int*)d_in[0];
    const float* emb   = (const float*)d_in[1];
    const float* W_ih0 = (const float*)d_in[2];
    const float* W_hh0 = (const float*)d_in[3];
    const float* b_ih0 = (const float*)d_in[4];
    const float* b_hh0 = (const float*)d_in[5];
    const float* W_ih1 = (const float*)d_in[6];
    const float* W_hh1 = (const float*)d_in[7];
    const float* b_ih1 = (const float*)d_in[8];
    const float* b_hh1 = (const float*)d_in[9];
    const float* fc_w  = (const float*)d_in[10];
    const float* fc_b  = (const float*)d_in[11];
    float*       out   = (float*)d_out;

    xproj_kernel<<<VOCAB, HID>>>(emb, W_ih0, b_ih0);
    scan_kernel<<<BATCH / ROWS_PER_CTA, 64 * ROWS_PER_CTA>>>(
        x_raw, W_hh0, b_hh0, W_ih1, W_hh1, b_ih1, b_hh1, fc_w, fc_b, out);
}